// round 4
// baseline (speedup 1.0000x reference)
#include <cuda_runtime.h>
#include <cstdint>

// Problem constants (fixed-shape problem).
constexpr int N_PTS    = 1048576;          // points
constexpr int C        = 64;               // channels
constexpr int GRID_DIM = 128;
constexpr int BATCH    = 4;
constexpr int VOXELS   = GRID_DIM * GRID_DIM * GRID_DIM * BATCH;  // 8,388,608
constexpr int WORDS    = VOXELS / 64;                             // 131,072

constexpr int SCAN_BLOCKS  = 256;   // 256 blocks * 256 threads * 2 words
constexpr int SCAN_THREADS = 256;

// ---------------------------------------------------------------------------
// Device scratch.
// ---------------------------------------------------------------------------
__device__ int                g_lin[N_PTS];       // point -> linear voxel id
__device__ unsigned long long g_bm[WORDS];        // occupancy bitmap   (1 MB)
__device__ unsigned long long g_mb[WORDS];        // multi-hit bitmap   (1 MB)
__device__ int                g_wordoff[WORDS];   // excl. rank prefix per word
__device__ unsigned int      g_status[SCAN_BLOCKS]; // lookback: val<<2 | flag
__device__ int                g_num_unique;
__device__ int                g_is64;             // coords dtype flag

// ---------------------------------------------------------------------------
__device__ __forceinline__ int warp_incl_scan(int v) {
    #pragma unroll
    for (int d = 1; d < 32; d <<= 1) {
        int n = __shfl_up_sync(0xffffffffu, v, d);
        if ((threadIdx.x & 31) >= d) v += n;
    }
    return v;
}

// ---------------------------------------------------------------------------
// 1. Zero bitmaps + scan status + parallel dtype detect (block 0, warp 0).
// ---------------------------------------------------------------------------
__global__ void k_init(const int* __restrict__ coords32) {
    int idx    = blockIdx.x * blockDim.x + threadIdx.x;
    int stride = gridDim.x * blockDim.x;
    ulonglong2 z = make_ulonglong2(0ull, 0ull);
    ulonglong2* p0 = reinterpret_cast<ulonglong2*>(g_bm);
    ulonglong2* p1 = reinterpret_cast<ulonglong2*>(g_mb);
    const int n2 = WORDS / 2;
    for (int i = idx; i < n2; i += stride) { p0[i] = z; p1[i] = z; }
    if (idx < SCAN_BLOCKS) g_status[idx] = 0u;

    if (blockIdx.x == 0 && threadIdx.x < 32) {
        int lane = threadIdx.x;
        int acc = 0;
        #pragma unroll
        for (int k = 0; k < 32; k++)                 // odd words of first 2048 ints
            acc |= coords32[1 + 2 * (lane + 32 * k)];
        #pragma unroll
        for (int d = 16; d; d >>= 1) acc |= __shfl_down_sync(0xffffffffu, acc, d);
        if (lane == 0) g_is64 = (acc == 0) ? 1 : 0;
    }
}

// ---------------------------------------------------------------------------
// 2. lin ids + occupancy / multi-hit bitmaps.
// ---------------------------------------------------------------------------
__global__ void k_count(const void* __restrict__ coords) {
    int p = blockIdx.x * blockDim.x + threadIdx.x;
    if (p >= N_PTS) return;
    int x, y, z, b;
    if (g_is64) {
        const longlong4 v = reinterpret_cast<const longlong4*>(coords)[p];
        x = (int)v.x; y = (int)v.y; z = (int)v.z; b = (int)v.w;
    } else {
        const int4 v = reinterpret_cast<const int4*>(coords)[p];
        x = v.x; y = v.y; z = v.z; b = v.w;
    }
    int lin = ((b * GRID_DIM + x) * GRID_DIM + y) * GRID_DIM + z;
    g_lin[p] = lin;
    unsigned long long mask = 1ull << (lin & 63);
    unsigned long long old  = atomicOr(&g_bm[lin >> 6], mask);
    if (old & mask) atomicOr(&g_mb[lin >> 6], mask);   // second+ arrival
}

// ---------------------------------------------------------------------------
// 3. Single-pass scan with decoupled lookback. Each block: 512 words.
//    Produces g_wordoff, sorted unique ids, pre-zeroed multi rows, num_unique.
//    All 256 blocks fit in one wave (148 SMs) -> lookback cannot deadlock.
// ---------------------------------------------------------------------------
__global__ void k_scan(float* __restrict__ out_uniq, float* __restrict__ out_feat) {
    __shared__ int sh_warp[SCAN_THREADS / 32];   // becomes exclusive warp offsets
    __shared__ int sh_total;
    __shared__ int sh_prefix;

    const int bid  = blockIdx.x;
    const int lane = threadIdx.x & 31, wid = threadIdx.x >> 5;

    int w0 = bid * (SCAN_THREADS * 2) + threadIdx.x * 2;
    ulonglong2 bmv = reinterpret_cast<const ulonglong2*>(g_bm)[w0 >> 1];
    int p0 = __popcll(bmv.x), p1 = __popcll(bmv.y);
    int s = p0 + p1;

    int incl = warp_incl_scan(s);
    if (lane == 31) sh_warp[wid] = incl;
    __syncthreads();

    // Warp 0: scan the 8 warp totals -> exclusive offsets; publish block total.
    if (wid == 0 && lane < SCAN_THREADS / 32) {
        int w = sh_warp[lane];
        int e = w;
        #pragma unroll
        for (int d = 1; d < SCAN_THREADS / 32; d <<= 1) {
            int n = __shfl_up_sync(0xffu, e, d);
            if (lane >= d) e += n;
        }
        sh_warp[lane] = e - w;                    // exclusive
        if (lane == SCAN_THREADS / 32 - 1) {
            sh_total = e;                         // block total
            unsigned int st = ((unsigned)e << 2) | (bid == 0 ? 2u : 1u);
            atomicExch(&g_status[bid], st);
        }
    }
    __syncthreads();

    // Warp 0: decoupled lookback for the running prefix.
    if (bid == 0) {
        if (threadIdx.x == 0) sh_prefix = 0;
    } else if (wid == 0) {
        int prefix = 0;
        int j = bid - 1;
        while (true) {
            int jj = j - lane;
            unsigned int st = 2u;                 // jj < 0: inclusive 0
            if (jj >= 0) {
                do { st = *(volatile unsigned int*)&g_status[jj]; }
                while ((st & 3u) == 0u);
            }
            unsigned int mask2 = __ballot_sync(0xffffffffu, (st & 3u) == 2u);
            if (mask2) {
                int firstlane = __ffs(mask2) - 1;     // largest jj with flag 2
                int contrib = (lane <= firstlane) ? (int)(st >> 2) : 0;
                #pragma unroll
                for (int d = 16; d; d >>= 1)
                    contrib += __shfl_xor_sync(0xffffffffu, contrib, d);
                prefix += contrib;
                break;
            } else {
                int contrib = (int)(st >> 2);
                #pragma unroll
                for (int d = 16; d; d >>= 1)
                    contrib += __shfl_xor_sync(0xffffffffu, contrib, d);
                prefix += contrib;
                j -= 32;
            }
        }
        if (lane == 0) {
            sh_prefix = prefix;
            atomicExch(&g_status[bid],
                       ((unsigned)(prefix + sh_total) << 2) | 2u);
            if (bid == SCAN_BLOCKS - 1) g_num_unique = prefix + sh_total;
        }
    }
    __syncthreads();

    int off = sh_prefix + sh_warp[wid] + incl - s;

    g_wordoff[w0]     = off;
    g_wordoff[w0 + 1] = off + p0;

    ulonglong2 mbv = reinterpret_cast<const ulonglong2*>(g_mb)[w0 >> 1];
    #pragma unroll
    for (int half = 0; half < 2; half++) {
        unsigned long long bm = half ? bmv.y : bmv.x;
        unsigned long long mb = half ? mbv.y : mbv.x;
        int w = w0 + half;
        int r = half ? (off + p0) : off;
        while (bm) {
            int b = __ffsll((long long)bm) - 1;
            bm &= bm - 1;
            int cell = (w << 6) | b;
            out_uniq[r] = (float)cell;              // ids < 2^23: exact in fp32
            if ((mb >> b) & 1) {                    // multi-hit: pre-zero row
                float4 zz = make_float4(0.f, 0.f, 0.f, 0.f);
                float4* row = reinterpret_cast<float4*>(out_feat + (size_t)r * C);
                #pragma unroll
                for (int j = 0; j < C / 4; j++) row[j] = zz;
            }
            r++;
        }
    }
}

// ---------------------------------------------------------------------------
// 4. Scatter + tail merged. 4 threads per point, 4 float4 each (contiguous
//    64 B per thread). Streaming cache hints on the 512 MB feature stream.
// ---------------------------------------------------------------------------
__global__ void k_scatter(const float* __restrict__ feat,
                          float* __restrict__ out_uniq,
                          float* __restrict__ out_feat) {
    int tid  = blockIdx.x * blockDim.x + threadIdx.x;   // N_PTS * 4 threads
    int pt   = tid >> 2, t = tid & 3;
    int lane = threadIdx.x & 31;

    // ---- tail: rows >= num_unique -> uniq=-1, feature row = 0 ----
    int nu = g_num_unique;
    if (pt >= nu) {
        if (t == 0) out_uniq[pt] = -1.0f;
        float4 z = make_float4(0.f, 0.f, 0.f, 0.f);
        float4* row = reinterpret_cast<float4*>(out_feat + (size_t)pt * C) + 4 * t;
        __stcs(&row[0], z); __stcs(&row[1], z);
        __stcs(&row[2], z); __stcs(&row[3], z);
    }

    // ---- rank (lanes 0,4,8,...,28 compute; broadcast to their group) ----
    int rr = 0;
    if ((lane & 3) == 0) {
        int lin = g_lin[pt];
        int w   = lin >> 6, b = lin & 63;
        unsigned long long bm = g_bm[w];
        int r = g_wordoff[w] + __popcll(bm & ((1ull << b) - 1ull));
        unsigned long long mb = g_mb[w];
        rr = r | (int)(((mb >> b) & 1ull) << 31);
    }
    rr = __shfl_sync(0xffffffffu, rr, lane & 28);

    int r = rr & 0x7fffffff;
    const float4* src = reinterpret_cast<const float4*>(feat) + (size_t)pt * (C / 4) + 4 * t;
    float4 v0 = __ldcs(&src[0]);
    float4 v1 = __ldcs(&src[1]);
    float4 v2 = __ldcs(&src[2]);
    float4 v3 = __ldcs(&src[3]);
    float* dst = out_feat + (size_t)r * C + t * 16;
    if (rr >= 0) {
        float4* d4 = reinterpret_cast<float4*>(dst);
        __stcs(&d4[0], v0); __stcs(&d4[1], v1);
        __stcs(&d4[2], v2); __stcs(&d4[3], v3);
    } else {
        atomicAdd(dst + 0,  v0.x); atomicAdd(dst + 1,  v0.y);
        atomicAdd(dst + 2,  v0.z); atomicAdd(dst + 3,  v0.w);
        atomicAdd(dst + 4,  v1.x); atomicAdd(dst + 5,  v1.y);
        atomicAdd(dst + 6,  v1.z); atomicAdd(dst + 7,  v1.w);
        atomicAdd(dst + 8,  v2.x); atomicAdd(dst + 9,  v2.y);
        atomicAdd(dst + 10, v2.z); atomicAdd(dst + 11, v2.w);
        atomicAdd(dst + 12, v3.x); atomicAdd(dst + 13, v3.y);
        atomicAdd(dst + 14, v3.z); atomicAdd(dst + 15, v3.w);
    }
}

// ---------------------------------------------------------------------------
extern "C" void kernel_launch(void* const* d_in, const int* in_sizes, int n_in,
                              void* d_out, int out_size) {
    const void*  coords = d_in[0];                    // [N,4] int64 or int32
    const float* feats  = (const float*)d_in[1];      // [N,64] float32
    (void)in_sizes; (void)n_in; (void)out_size;

    float* out      = (float*)d_out;
    float* out_uniq = out;                            // [N]
    float* out_feat = out + N_PTS;                    // [N,64], 16B-aligned

    k_init<<<256, 256>>>((const int*)coords);
    k_count<<<N_PTS / 256, 256>>>(coords);
    k_scan<<<SCAN_BLOCKS, SCAN_THREADS>>>(out_uniq, out_feat);
    k_scatter<<<(N_PTS * 4) / 256, 256>>>(feats, out_uniq, out_feat);
}

// round 6
// speedup vs baseline: 1.1510x; 1.1510x over previous
#include <cuda_runtime.h>
#include <cstdint>

// Problem constants (fixed-shape problem).
constexpr int N_PTS    = 1048576;          // points
constexpr int C        = 64;               // channels
constexpr int GRID_DIM = 128;
constexpr int BATCH    = 4;
constexpr int VOXELS   = GRID_DIM * GRID_DIM * GRID_DIM * BATCH;  // 8,388,608
constexpr int WORDS    = VOXELS / 64;                             // 131,072

constexpr int SCAN_BLOCKS  = 256;   // 256 blocks * 256 threads * 2 words
constexpr int SCAN_THREADS = 256;

// ---------------------------------------------------------------------------
// Device scratch.
// ---------------------------------------------------------------------------
__device__ int                g_lin[N_PTS];       // point -> linear voxel id
__device__ unsigned long long g_bm[WORDS];        // occupancy bitmap   (1 MB)
__device__ unsigned long long g_mb[WORDS];        // multi-hit bitmap   (1 MB)
__device__ int                g_wordoff[WORDS];   // excl. rank prefix per word
__device__ unsigned int       g_status[SCAN_BLOCKS]; // lookback: val<<2 | flag
__device__ int                g_num_unique;
__device__ int                g_is64;             // coords dtype flag

// ---------------------------------------------------------------------------
__device__ __forceinline__ int warp_incl_scan(int v) {
    #pragma unroll
    for (int d = 1; d < 32; d <<= 1) {
        int n = __shfl_up_sync(0xffffffffu, v, d);
        if ((threadIdx.x & 31) >= d) v += n;
    }
    return v;
}

// ---------------------------------------------------------------------------
// 1. Zero bitmaps + scan status + parallel dtype detect (block 0, warp 0).
// ---------------------------------------------------------------------------
__global__ void k_init(const int* __restrict__ coords32) {
    int idx    = blockIdx.x * blockDim.x + threadIdx.x;
    int stride = gridDim.x * blockDim.x;
    ulonglong2 z = make_ulonglong2(0ull, 0ull);
    ulonglong2* p0 = reinterpret_cast<ulonglong2*>(g_bm);
    ulonglong2* p1 = reinterpret_cast<ulonglong2*>(g_mb);
    const int n2 = WORDS / 2;
    for (int i = idx; i < n2; i += stride) { p0[i] = z; p1[i] = z; }
    if (idx < SCAN_BLOCKS) g_status[idx] = 0u;

    if (blockIdx.x == 0 && threadIdx.x < 32) {
        int lane = threadIdx.x;
        int acc = 0;
        #pragma unroll
        for (int k = 0; k < 32; k++)                 // odd words of first 2048 ints
            acc |= coords32[1 + 2 * (lane + 32 * k)];
        #pragma unroll
        for (int d = 16; d; d >>= 1) acc |= __shfl_down_sync(0xffffffffu, acc, d);
        if (lane == 0) g_is64 = (acc == 0) ? 1 : 0;
    }
}

// ---------------------------------------------------------------------------
// 2. lin ids + occupancy / multi-hit bitmaps.
// ---------------------------------------------------------------------------
__global__ void k_count(const void* __restrict__ coords) {
    int p = blockIdx.x * blockDim.x + threadIdx.x;
    if (p >= N_PTS) return;
    int x, y, z, b;
    if (g_is64) {
        const longlong4 v = reinterpret_cast<const longlong4*>(coords)[p];
        x = (int)v.x; y = (int)v.y; z = (int)v.z; b = (int)v.w;
    } else {
        const int4 v = reinterpret_cast<const int4*>(coords)[p];
        x = v.x; y = v.y; z = v.z; b = v.w;
    }
    int lin = ((b * GRID_DIM + x) * GRID_DIM + y) * GRID_DIM + z;
    g_lin[p] = lin;
    unsigned long long mask = 1ull << (lin & 63);
    unsigned long long old  = atomicOr(&g_bm[lin >> 6], mask);
    if (old & mask) atomicOr(&g_mb[lin >> 6], mask);   // second+ arrival
}

// ---------------------------------------------------------------------------
// 3. Single-pass scan with decoupled lookback. Each block: 512 words.
//    Produces g_wordoff, sorted unique ids, pre-zeroed multi rows, num_unique.
//    All 256 blocks fit in one wave (148 SMs) -> lookback cannot deadlock.
// ---------------------------------------------------------------------------
__global__ void k_scan(float* __restrict__ out_uniq, float* __restrict__ out_feat) {
    __shared__ int sh_warp[SCAN_THREADS / 32];   // becomes exclusive warp offsets
    __shared__ int sh_total;
    __shared__ int sh_prefix;

    const int bid  = blockIdx.x;
    const int lane = threadIdx.x & 31, wid = threadIdx.x >> 5;

    int w0 = bid * (SCAN_THREADS * 2) + threadIdx.x * 2;
    ulonglong2 bmv = reinterpret_cast<const ulonglong2*>(g_bm)[w0 >> 1];
    int p0 = __popcll(bmv.x), p1 = __popcll(bmv.y);
    int s = p0 + p1;

    int incl = warp_incl_scan(s);
    if (lane == 31) sh_warp[wid] = incl;
    __syncthreads();

    // Warp 0: scan the 8 warp totals -> exclusive offsets; publish block total.
    if (wid == 0 && lane < SCAN_THREADS / 32) {
        int w = sh_warp[lane];
        int e = w;
        #pragma unroll
        for (int d = 1; d < SCAN_THREADS / 32; d <<= 1) {
            int n = __shfl_up_sync(0xffu, e, d);
            if (lane >= d) e += n;
        }
        sh_warp[lane] = e - w;                    // exclusive
        if (lane == SCAN_THREADS / 32 - 1) {
            sh_total = e;                         // block total
            unsigned int st = ((unsigned)e << 2) | (bid == 0 ? 2u : 1u);
            atomicExch(&g_status[bid], st);
        }
    }
    __syncthreads();

    // Warp 0: decoupled lookback for the running prefix.
    if (bid == 0) {
        if (threadIdx.x == 0) sh_prefix = 0;
    } else if (wid == 0) {
        int prefix = 0;
        int j = bid - 1;
        while (true) {
            int jj = j - lane;
            unsigned int st = 2u;                 // jj < 0: inclusive 0
            if (jj >= 0) {
                do { st = *(volatile unsigned int*)&g_status[jj]; }
                while ((st & 3u) == 0u);
            }
            unsigned int mask2 = __ballot_sync(0xffffffffu, (st & 3u) == 2u);
            if (mask2) {
                int firstlane = __ffs(mask2) - 1;     // largest jj with flag 2
                int contrib = (lane <= firstlane) ? (int)(st >> 2) : 0;
                #pragma unroll
                for (int d = 16; d; d >>= 1)
                    contrib += __shfl_xor_sync(0xffffffffu, contrib, d);
                prefix += contrib;
                break;
            } else {
                int contrib = (int)(st >> 2);
                #pragma unroll
                for (int d = 16; d; d >>= 1)
                    contrib += __shfl_xor_sync(0xffffffffu, contrib, d);
                prefix += contrib;
                j -= 32;
            }
        }
        if (lane == 0) {
            sh_prefix = prefix;
            atomicExch(&g_status[bid],
                       ((unsigned)(prefix + sh_total) << 2) | 2u);
            if (bid == SCAN_BLOCKS - 1) g_num_unique = prefix + sh_total;
        }
    }
    __syncthreads();

    int off = sh_prefix + sh_warp[wid] + incl - s;

    g_wordoff[w0]     = off;
    g_wordoff[w0 + 1] = off + p0;

    ulonglong2 mbv = reinterpret_cast<const ulonglong2*>(g_mb)[w0 >> 1];
    #pragma unroll
    for (int half = 0; half < 2; half++) {
        unsigned long long bm = half ? bmv.y : bmv.x;
        unsigned long long mb = half ? mbv.y : mbv.x;
        int w = w0 + half;
        int r = half ? (off + p0) : off;
        while (bm) {
            int b = __ffsll((long long)bm) - 1;
            bm &= bm - 1;
            int cell = (w << 6) | b;
            out_uniq[r] = (float)cell;              // ids < 2^23: exact in fp32
            if ((mb >> b) & 1) {                    // multi-hit: pre-zero row
                float4 zz = make_float4(0.f, 0.f, 0.f, 0.f);
                float4* row = reinterpret_cast<float4*>(out_feat + (size_t)r * C);
                #pragma unroll
                for (int j = 0; j < C / 4; j++) row[j] = zz;
            }
            r++;
        }
    }
}

// ---------------------------------------------------------------------------
// 4. Scatter + tail merged. 8 threads per point, 2 float4 each (proven best
//    divergence/MLP tradeoff: 4 points/warp). Feature loads issued before the
//    dependent rank-lookup chain; rank computed on all lanes (broadcast loads,
//    no shuffle serialization). Streaming hints on the 512 MB stream.
// ---------------------------------------------------------------------------
__global__ void k_scatter(const float* __restrict__ feat,
                          float* __restrict__ out_uniq,
                          float* __restrict__ out_feat) {
    int tid = blockIdx.x * blockDim.x + threadIdx.x;   // N_PTS * 8 threads
    int pt  = tid >> 3, t = tid & 7;

    // Independent 256 B feature stream: issue first.
    const float4* src = reinterpret_cast<const float4*>(feat) + (size_t)pt * (C / 4) + 2 * t;
    float4 v0 = __ldcs(&src[0]);
    float4 v1 = __ldcs(&src[1]);

    // Rank lookup (same addresses across the 8-lane group -> L1 broadcast).
    int lin = g_lin[pt];
    int w   = lin >> 6, b = lin & 63;
    unsigned long long bm = g_bm[w];
    unsigned long long mb = g_mb[w];
    int r = g_wordoff[w] + __popcll(bm & ((1ull << b) - 1ull));
    bool multi = (mb >> b) & 1ull;

    // Tail: rows >= num_unique -> uniq=-1, feature row = 0.
    int nu = g_num_unique;
    if (pt >= nu) {
        if (t == 0) out_uniq[pt] = -1.0f;
        float4 z = make_float4(0.f, 0.f, 0.f, 0.f);
        float4* row = reinterpret_cast<float4*>(out_feat + (size_t)pt * C) + 2 * t;
        __stcs(&row[0], z);
        __stcs(&row[1], z);
    }

    float* dst = out_feat + (size_t)r * C + t * 8;
    if (!multi) {
        float4* d4 = reinterpret_cast<float4*>(dst);
        __stcs(&d4[0], v0);
        __stcs(&d4[1], v1);
    } else {
        atomicAdd(dst + 0, v0.x); atomicAdd(dst + 1, v0.y);
        atomicAdd(dst + 2, v0.z); atomicAdd(dst + 3, v0.w);
        atomicAdd(dst + 4, v1.x); atomicAdd(dst + 5, v1.y);
        atomicAdd(dst + 6, v1.z); atomicAdd(dst + 7, v1.w);
    }
}

// ---------------------------------------------------------------------------
extern "C" void kernel_launch(void* const* d_in, const int* in_sizes, int n_in,
                              void* d_out, int out_size) {
    const void*  coords = d_in[0];                    // [N,4] int64 or int32
    const float* feats  = (const float*)d_in[1];      // [N,64] float32
    (void)in_sizes; (void)n_in; (void)out_size;

    float* out      = (float*)d_out;
    float* out_uniq = out;                            // [N]
    float* out_feat = out + N_PTS;                    // [N,64], 16B-aligned

    k_init<<<256, 256>>>((const int*)coords);
    k_count<<<N_PTS / 256, 256>>>(coords);
    k_scan<<<SCAN_BLOCKS, SCAN_THREADS>>>(out_uniq, out_feat);
    k_scatter<<<(N_PTS * 8) / 256, 256>>>(feats, out_uniq, out_feat);
}